// round 15
// baseline (speedup 1.0000x reference)
#include <cuda_runtime.h>
#include <cuda_fp16.h>
#include <math.h>

#define NN 100000
#define EE 3200000
#define FIN 256
#define CC1 32
#define CC2 64
#define HH 128
#define NCLS 10
#define CAP 128            // bucket capacity per node (max observed degree ~75)

typedef unsigned long long ull;

// ---------------- scratch (__device__ globals; no allocation allowed) ----------------
__device__ int    g_cur[NN];                 // zero-init; self-reset by gatherg each run
__device__ ull    g_csr[(size_t)NN * CAP];   // packed (half2(w,w)<<32 | src), bucketed
__device__ __half g_wcat1[96 * FIN];         // conv1 WcatT[n][k] fp16
__device__ __half g_wcat2f[CC2 * 96];        // fused conv2 W[n][k]: [W2a | W2c | -W2b] fp16
__device__ __half g_wf1t[HH * CC2];          // fc1 WT[n][k] fp16

__device__ __half g_a1[NN * CC1];    // conv1 lin1 table, fp16
__device__ __half g_b1[NN * CC1];    // conv1 lin2 table, fp16
__device__ __half g_c1[NN * CC1];    // conv1 lin3 table, fp16
__device__ __half g_h1[NN * CC1];    // conv1 output, fp16
__device__ float  g_wsum[NN];        // per-node sum of edge weights
__device__ __half g_g[NN * CC1];     // G = sum_e w*h1[src], fp16
__device__ __half g_h2[NN * CC2];    // conv2 output, fp16

__device__ __forceinline__ float elu1(float v) {
    return v > 0.0f ? v : expm1f(v);
}

__device__ __forceinline__ __half2 h2_from_bits(unsigned u) {
    __half2 h;
    *(unsigned*)&h = u;
    return h;
}

// ---------------- bucketed CSR build: scatter only (g_cur self-resets) ----------------
__device__ __forceinline__ void scat1(int d, int s, float w) {
    int p = atomicAdd(&g_cur[d], 1);
    if (p < CAP) {
        unsigned hb = (unsigned)__half_as_ushort(__float2half(w));
        unsigned w2 = hb | (hb << 16);
        ull pack = ((ull)w2 << 32) | (unsigned)s;
        g_csr[(size_t)d * CAP + p] = pack;
    }
}

__global__ void scatter_kernel(const int4* __restrict__ src4, const int4* __restrict__ dst4,
                               const float4* __restrict__ ew4) {
    int e4 = blockIdx.x * blockDim.x + threadIdx.x;
    if (e4 < EE / 4) {
        int4   s = src4[e4];
        int4   d = dst4[e4];
        float4 w = ew4[e4];
        scat1(d.x, s.x, w.x);
        scat1(d.y, s.y, w.y);
        scat1(d.z, s.z, w.z);
        scat1(d.w, s.w, w.w);
    }
}

// ---------------- W prep ----------------
#define PREPW_TOTAL (96 * FIN + CC2 * 96 + HH * CC2)
__global__ void prep_w_kernel(const float* __restrict__ W1a, const float* __restrict__ W1b,
                              const float* __restrict__ W1c,
                              const float* __restrict__ W2a, const float* __restrict__ W2b,
                              const float* __restrict__ W2c,
                              const float* __restrict__ Wf1) {
    int idx = blockIdx.x * blockDim.x + threadIdx.x;
    if (idx < 96 * FIN) {
        int nn = idx / FIN, k = idx % FIN;
        float v = (nn < 32) ? W1a[k * 32 + nn]
                : (nn < 64) ? W1b[k * 32 + (nn - 32)]
                            : W1c[k * 32 + (nn - 64)];
        g_wcat1[idx] = __float2half(v);
    } else if (idx < 96 * FIN + CC2 * 96) {
        int j = idx - 96 * FIN;
        int nn = j / 96, k = j % 96;
        float v = (k < 32) ? W2a[k * 64 + nn]
                : (k < 64) ? W2c[(k - 32) * 64 + nn]
                           : -W2b[(k - 64) * 64 + nn];
        g_wcat2f[j] = __float2half(v);
    } else if (idx < PREPW_TOTAL) {
        int j = idx - 96 * FIN - CC2 * 96;
        int nn = j / CC2, k = j % CC2;
        g_wf1t[j] = __float2half(Wf1[k * HH + nn]);
    }
}

// ================= conv1 GEMM: HMMA, M=64 tile, warp-split N, K dbuf 64 =================
#define XP 72
#define GEMM1_SMEM ((2 * 64 * XP + 2 * 96 * XP) * 2)   // 46080 bytes
__global__ __launch_bounds__(256)
void gemm1_tc_kernel(const float* __restrict__ X,
                     const float* __restrict__ b0v, const float* __restrict__ b2v,
                     __half* __restrict__ outA, __half* __restrict__ outB,
                     __half* __restrict__ outC, int n) {
    extern __shared__ __half smem[];
    __half* sX = smem;                   // [2][64][XP]
    __half* sW = smem + 2 * 64 * XP;     // [2][96][XP]

    int tid = threadIdx.x;
    int wid = tid >> 5;
    int lane = tid & 31;
    int gid = lane >> 2;
    int tig = lane & 3;
    int mgrp = wid & 3;
    int nhalf = wid >> 2;
    int m0 = blockIdx.x * 64;

    auto loadX = [&](int buf, int kt) {
        __half* dst = sX + buf * 64 * XP;
#pragma unroll
        for (int i = tid; i < 64 * 16; i += 256) {
            int m = i >> 4, kq = i & 15;
            int gm = m0 + m;
            float4 v = make_float4(0.f, 0.f, 0.f, 0.f);
            if (gm < n) v = *(const float4*)&X[(size_t)gm * FIN + kt + kq * 4];
            *(__half2*)&dst[m * XP + kq * 4]     = __floats2half2_rn(v.x, v.y);
            *(__half2*)&dst[m * XP + kq * 4 + 2] = __floats2half2_rn(v.z, v.w);
        }
    };
    auto loadW = [&](int buf, int kt) {
        __half* dst = sW + buf * 96 * XP;
#pragma unroll
        for (int i = tid; i < 96 * 8; i += 256) {
            int nn = i >> 3, kq = i & 7;
            *(int4*)&dst[nn * XP + kq * 8] = *(const int4*)&g_wcat1[nn * FIN + kt + kq * 8];
        }
    };

    loadX(0, 0); loadW(0, 0);
    __syncthreads();

    float acc[6][4];
#pragma unroll
    for (int t = 0; t < 6; t++)
#pragma unroll
        for (int j = 0; j < 4; j++) acc[t][j] = 0.0f;

    int rowA = mgrp * 16 + gid;
#pragma unroll
    for (int c = 0; c < 4; c++) {
        int buf = c & 1;
        if (c < 3) { loadX(buf ^ 1, (c + 1) * 64); loadW(buf ^ 1, (c + 1) * 64); }
        const __half* bX = sX + buf * 64 * XP;
        const __half* bW = sW + buf * 96 * XP;
#pragma unroll
        for (int kt = 0; kt < 64; kt += 16) {
            unsigned a0 = *(const unsigned*)&bX[rowA * XP + kt + 2 * tig];
            unsigned a1 = *(const unsigned*)&bX[(rowA + 8) * XP + kt + 2 * tig];
            unsigned a2 = *(const unsigned*)&bX[rowA * XP + kt + 8 + 2 * tig];
            unsigned a3 = *(const unsigned*)&bX[(rowA + 8) * XP + kt + 8 + 2 * tig];
#pragma unroll
            for (int nt = 0; nt < 6; nt++) {
                int nn = nhalf * 48 + nt * 8 + gid;
                unsigned bb0 = *(const unsigned*)&bW[nn * XP + kt + 2 * tig];
                unsigned bb1 = *(const unsigned*)&bW[nn * XP + kt + 8 + 2 * tig];
                asm volatile(
                    "mma.sync.aligned.m16n8k16.row.col.f32.f16.f16.f32 "
                    "{%0,%1,%2,%3}, {%4,%5,%6,%7}, {%8,%9}, {%0,%1,%2,%3};"
                    : "+f"(acc[nt][0]), "+f"(acc[nt][1]), "+f"(acc[nt][2]), "+f"(acc[nt][3])
                    : "r"(a0), "r"(a1), "r"(a2), "r"(a3), "r"(bb0), "r"(bb1));
            }
        }
        __syncthreads();
    }

    int node0 = m0 + rowA;
    int node1 = node0 + 8;
#pragma unroll
    for (int nt = 0; nt < 6; nt++) {
        int c0 = nhalf * 48 + nt * 8 + 2 * tig;
        if (c0 < 32) {
            float ba0 = b0v[c0], ba1 = b0v[c0 + 1];
            if (node0 < n)
                *(__half2*)&outA[(size_t)node0 * 32 + c0] = __floats2half2_rn(acc[nt][0] + ba0, acc[nt][1] + ba1);
            if (node1 < n)
                *(__half2*)&outA[(size_t)node1 * 32 + c0] = __floats2half2_rn(acc[nt][2] + ba0, acc[nt][3] + ba1);
        } else if (c0 < 64) {
            int cc = c0 - 32;
            if (node0 < n)
                *(__half2*)&outB[(size_t)node0 * 32 + cc] = __floats2half2_rn(acc[nt][0], acc[nt][1]);
            if (node1 < n)
                *(__half2*)&outB[(size_t)node1 * 32 + cc] = __floats2half2_rn(acc[nt][2], acc[nt][3]);
        } else {
            int cc = c0 - 64;
            float bc0 = b2v[cc], bc1 = b2v[cc + 1];
            if (node0 < n)
                *(__half2*)&outC[(size_t)node0 * 32 + cc] = __floats2half2_rn(acc[nt][0] + bc0, acc[nt][1] + bc1);
            if (node1 < n)
                *(__half2*)&outC[(size_t)node1 * 32 + cc] = __floats2half2_rn(acc[nt][2] + bc0, acc[nt][3] + bc1);
        }
    }
}

// ---------------- gather32: warp/node, even/odd halves, HFMA2 inner loop ----------------
#define G32_NPB 8
__global__ __launch_bounds__(256)
void gather32_kernel(const __half2* __restrict__ Ah2, const __half2* __restrict__ Bh2,
                     const __half2* __restrict__ Ch2, __half* __restrict__ H,
                     float* __restrict__ wsv, int n) {
    __shared__ ull se[G32_NPB * CAP];
    __shared__ int scnt[G32_NPB];
    int base = blockIdx.x * G32_NPB;
    int tid = threadIdx.x;
    int wid = tid >> 5, lane = tid & 31;
    int sub = lane & 15, hf = lane >> 4;

    if (tid < G32_NPB) {
        int nd = base + tid;
        int c = (nd < n) ? g_cur[nd] : 0;
        scnt[tid] = c < CAP ? c : CAP;
    }
    __syncthreads();
    for (int i = tid; i < G32_NPB * CAP; i += 256) {
        int slot = i >> 7, off = i & (CAP - 1);
        if (off < scnt[slot]) se[i] = g_csr[(size_t)(base + slot) * CAP + off];
    }
    __syncthreads();

    int node = base + wid;
    if (node >= n) return;

    int cnt = scnt[wid];
    const ull* eb = &se[wid * CAP];
    float ax = 0.0f, ay = 0.0f, wsum = 0.0f;
    __half2 zero2 = __floats2half2_rn(0.0f, 0.0f);
    int e = hf;
    for (; e + 14 < cnt; e += 16) {
        ull p[8];
#pragma unroll
        for (int j = 0; j < 8; j++) p[j] = eb[e + 2 * j];
        __half2 f[8];
#pragma unroll
        for (int j = 0; j < 8; j++) {
            int s = (int)(unsigned int)p[j];
            f[j] = Ah2[(size_t)s * 16 + sub];
        }
        __half2 acch = zero2, wsh = zero2;
#pragma unroll
        for (int j = 0; j < 8; j++) {
            __half2 w2 = h2_from_bits((unsigned int)(p[j] >> 32));
            acch = __hfma2(w2, f[j], acch);
            wsh  = __hadd2(wsh, w2);
        }
        float2 fa = __half22float2(acch);
        ax += fa.x; ay += fa.y;
        wsum += __low2float(wsh);
    }
    {
        __half2 acch = zero2, wsh = zero2;
        for (; e < cnt; e += 2) {
            ull p = eb[e];
            int s = (int)(unsigned int)p;
            __half2 w2 = h2_from_bits((unsigned int)(p >> 32));
            acch = __hfma2(w2, Ah2[(size_t)s * 16 + sub], acch);
            wsh  = __hadd2(wsh, w2);
        }
        float2 fa = __half22float2(acch);
        ax += fa.x; ay += fa.y;
        wsum += __low2float(wsh);
    }
    ax   += __shfl_xor_sync(0xFFFFFFFFu, ax, 16);
    ay   += __shfl_xor_sync(0xFFFFFFFFu, ay, 16);
    wsum += __shfl_xor_sync(0xFFFFFFFFu, wsum, 16);

    if (hf == 0) {
        float2 bv = __half22float2(Bh2[(size_t)node * 16 + sub]);
        float2 cv = __half22float2(Ch2[(size_t)node * 16 + sub]);
        __half2 o = __floats2half2_rn(elu1(ax - wsum * bv.x + cv.x),
                                      elu1(ay - wsum * bv.y + cv.y));
        *(__half2*)&H[(size_t)node * CC1 + 2 * sub] = o;
        if (sub == 0) wsv[node] = wsum;
    }
}

// ---------------- gatherg: aggregate h1 -> G (HFMA2); resets g_cur ----------------
__global__ __launch_bounds__(256)
void gatherg_kernel(const __half2* __restrict__ Hh2, __half* __restrict__ G, int n) {
    __shared__ ull se[G32_NPB * CAP];
    __shared__ int scnt[G32_NPB];
    int base = blockIdx.x * G32_NPB;
    int tid = threadIdx.x;
    int wid = tid >> 5, lane = tid & 31;
    int sub = lane & 15, hf = lane >> 4;

    if (tid < G32_NPB) {
        int nd = base + tid;
        int c = (nd < n) ? g_cur[nd] : 0;
        scnt[tid] = c < CAP ? c : CAP;
    }
    __syncthreads();
    // self-reset counters for the next launch (deterministic; last consumer)
    if (tid < G32_NPB && base + tid < n) g_cur[base + tid] = 0;
    for (int i = tid; i < G32_NPB * CAP; i += 256) {
        int slot = i >> 7, off = i & (CAP - 1);
        if (off < scnt[slot]) se[i] = g_csr[(size_t)(base + slot) * CAP + off];
    }
    __syncthreads();

    int node = base + wid;
    if (node >= n) return;

    int cnt = scnt[wid];
    const ull* eb = &se[wid * CAP];
    float ax = 0.0f, ay = 0.0f;
    __half2 zero2 = __floats2half2_rn(0.0f, 0.0f);
    int e = hf;
    for (; e + 14 < cnt; e += 16) {
        ull p[8];
#pragma unroll
        for (int j = 0; j < 8; j++) p[j] = eb[e + 2 * j];
        __half2 f[8];
#pragma unroll
        for (int j = 0; j < 8; j++) {
            int s = (int)(unsigned int)p[j];
            f[j] = Hh2[(size_t)s * 16 + sub];
        }
        __half2 acch = zero2;
#pragma unroll
        for (int j = 0; j < 8; j++) {
            __half2 w2 = h2_from_bits((unsigned int)(p[j] >> 32));
            acch = __hfma2(w2, f[j], acch);
        }
        float2 fa = __half22float2(acch);
        ax += fa.x; ay += fa.y;
    }
    {
        __half2 acch = zero2;
        for (; e < cnt; e += 2) {
            ull p = eb[e];
            int s = (int)(unsigned int)p;
            __half2 w2 = h2_from_bits((unsigned int)(p >> 32));
            acch = __hfma2(w2, Hh2[(size_t)s * 16 + sub], acch);
        }
        float2 fa = __half22float2(acch);
        ax += fa.x; ay += fa.y;
    }
    ax += __shfl_xor_sync(0xFFFFFFFFu, ax, 16);
    ay += __shfl_xor_sync(0xFFFFFFFFu, ay, 16);

    if (hf == 0)
        *(__half2*)&G[(size_t)node * CC1 + 2 * sub] = __floats2half2_rn(ax, ay);
}

// ================= fused conv2 GEMM: h2 = elu([G,h1,ws*h1] @ Wcat + ws*b2a + b2c) =================
#define AP 104   // K=96 + pad
__global__ __launch_bounds__(256)
void gemm2f_kernel(const __half* __restrict__ h1, const __half* __restrict__ G,
                   const float* __restrict__ wsv,
                   const float* __restrict__ b2a, const float* __restrict__ b2c,
                   __half* __restrict__ h2, int n) {
    __shared__ __half sA[64 * AP];
    __shared__ __half sW[64 * AP];

    int tid = threadIdx.x;
    int wid = tid >> 5;
    int lane = tid & 31;
    int gid = lane >> 2;
    int tig = lane & 3;
    int mgrp = wid & 3;
    int nhalf = wid >> 2;
    int m0 = blockIdx.x * 64;

    // build A rows: [G(0..31) | h1(32..63) | ws*h1(64..95)]
    for (int i = tid; i < 64 * 12; i += 256) {
        int m = i / 12, kq = i % 12;
        int gm = m0 + m;
        if (kq < 4) {
            int4 v = make_int4(0, 0, 0, 0);
            if (gm < n) v = *(const int4*)&G[(size_t)gm * 32 + kq * 8];
            *(int4*)&sA[m * AP + kq * 8] = v;
        } else if (kq < 8) {
            int4 v = make_int4(0, 0, 0, 0);
            if (gm < n) v = *(const int4*)&h1[(size_t)gm * 32 + (kq - 4) * 8];
            *(int4*)&sA[m * AP + 32 + (kq - 4) * 8] = v;
        } else {
            __half2 hv[4] = {__half2{}, __half2{}, __half2{}, __half2{}};
            if (gm < n) {
                float ws = wsv[gm];
#pragma unroll
                for (int q = 0; q < 4; q++) {
                    float2 f = __half22float2(*(const __half2*)&h1[(size_t)gm * 32 + (kq - 8) * 8 + 2 * q]);
                    hv[q] = __floats2half2_rn(ws * f.x, ws * f.y);
                }
            }
            *(int4*)&sA[m * AP + 64 + (kq - 8) * 8] = *(int4*)hv;
        }
    }
    for (int i = tid; i < 64 * 12; i += 256) {
        int nn = i / 12, kq = i % 12;
        *(int4*)&sW[nn * AP + kq * 8] = *(const int4*)&g_wcat2f[nn * 96 + kq * 8];
    }
    __syncthreads();

    float acc[4][4];
#pragma unroll
    for (int t = 0; t < 4; t++)
#pragma unroll
        for (int j = 0; j < 4; j++) acc[t][j] = 0.0f;

    int rowA = mgrp * 16 + gid;
#pragma unroll
    for (int kt = 0; kt < 96; kt += 16) {
        unsigned a0 = *(const unsigned*)&sA[rowA * AP + kt + 2 * tig];
        unsigned a1 = *(const unsigned*)&sA[(rowA + 8) * AP + kt + 2 * tig];
        unsigned a2 = *(const unsigned*)&sA[rowA * AP + kt + 8 + 2 * tig];
        unsigned a3 = *(const unsigned*)&sA[(rowA + 8) * AP + kt + 8 + 2 * tig];
#pragma unroll
        for (int nt = 0; nt < 4; nt++) {
            int nn = nhalf * 32 + nt * 8 + gid;
            unsigned bb0 = *(const unsigned*)&sW[nn * AP + kt + 2 * tig];
            unsigned bb1 = *(const unsigned*)&sW[nn * AP + kt + 8 + 2 * tig];
            asm volatile(
                "mma.sync.aligned.m16n8k16.row.col.f32.f16.f16.f32 "
                "{%0,%1,%2,%3}, {%4,%5,%6,%7}, {%8,%9}, {%0,%1,%2,%3};"
                : "+f"(acc[nt][0]), "+f"(acc[nt][1]), "+f"(acc[nt][2]), "+f"(acc[nt][3])
                : "r"(a0), "r"(a1), "r"(a2), "r"(a3), "r"(bb0), "r"(bb1));
        }
    }

    int node0 = m0 + rowA;
    int node1 = node0 + 8;
    float ws0 = (node0 < n) ? wsv[node0] : 0.0f;
    float ws1 = (node1 < n) ? wsv[node1] : 0.0f;
#pragma unroll
    for (int nt = 0; nt < 4; nt++) {
        int c = nhalf * 32 + nt * 8 + 2 * tig;
        float ba0 = b2a[c], ba1 = b2a[c + 1];
        float bc0 = b2c[c], bc1 = b2c[c + 1];
        if (node0 < n)
            *(__half2*)&h2[(size_t)node0 * 64 + c] =
                __floats2half2_rn(elu1(acc[nt][0] + ws0 * ba0 + bc0),
                                  elu1(acc[nt][1] + ws0 * ba1 + bc1));
        if (node1 < n)
            *(__half2*)&h2[(size_t)node1 * 64 + c] =
                __floats2half2_rn(elu1(acc[nt][2] + ws1 * ba0 + bc0),
                                  elu1(acc[nt][3] + ws1 * ba1 + bc1));
    }
}

// ================= fused fc1+fc2+log_softmax =================
#define XFP 72
#define HSP 136
__global__ __launch_bounds__(256)
void fc12_kernel(const __half* __restrict__ Xh, const float* __restrict__ bf1,
                 const float* __restrict__ Wf2, const float* __restrict__ bf2,
                 float* __restrict__ out, int n) {
    extern __shared__ __half dsm[];
    __half* sX  = dsm;               // [64][XFP]
    __half* sW1 = dsm + 64 * XFP;    // [128][XFP]
    __half* sH  = dsm;               // [64][HSP] alias (used after phase A)
    __shared__ float sWf2[NCLS * HH];
    __shared__ float sbf2[NCLS];

    int tid = threadIdx.x;
    int wid = tid >> 5;
    int lane = tid & 31;
    int gid = lane >> 2;
    int tig = lane & 3;
    int mgrp = wid & 3;
    int nhalf = wid >> 2;
    int m0 = blockIdx.x * 64;

    for (int i = tid; i < 64 * 8; i += 256) {
        int m = i >> 3, kq = i & 7;
        int gm = m0 + m;
        int4 v = make_int4(0, 0, 0, 0);
        if (gm < n) v = *(const int4*)&Xh[(size_t)gm * 64 + kq * 8];
        *(int4*)&sX[m * XFP + kq * 8] = v;
    }
    for (int i = tid; i < 128 * 8; i += 256) {
        int nn = i >> 3, kq = i & 7;
        *(int4*)&sW1[nn * XFP + kq * 8] = *(const int4*)&g_wf1t[nn * 64 + kq * 8];
    }
    for (int i = tid; i < HH * NCLS; i += 256) {
        int k = i / NCLS, c = i % NCLS;
        sWf2[c * HH + k] = Wf2[i];
    }
    if (tid < NCLS) sbf2[tid] = bf2[tid];
    __syncthreads();

    float acc[8][4];
#pragma unroll
    for (int t = 0; t < 8; t++)
#pragma unroll
        for (int j = 0; j < 4; j++) acc[t][j] = 0.0f;

    int rowA = mgrp * 16 + gid;
#pragma unroll
    for (int kt = 0; kt < 64; kt += 16) {
        unsigned a0 = *(const unsigned*)&sX[rowA * XFP + kt + 2 * tig];
        unsigned a1 = *(const unsigned*)&sX[(rowA + 8) * XFP + kt + 2 * tig];
        unsigned a2 = *(const unsigned*)&sX[rowA * XFP + kt + 8 + 2 * tig];
        unsigned a3 = *(const unsigned*)&sX[(rowA + 8) * XFP + kt + 8 + 2 * tig];
#pragma unroll
        for (int nt = 0; nt < 8; nt++) {
            int nn = (nhalf * 8 + nt) * 8 + gid;
            unsigned bb0 = *(const unsigned*)&sW1[nn * XFP + kt + 2 * tig];
            unsigned bb1 = *(const unsigned*)&sW1[nn * XFP + kt + 8 + 2 * tig];
            asm volatile(
                "mma.sync.aligned.m16n8k16.row.col.f32.f16.f16.f32 "
                "{%0,%1,%2,%3}, {%4,%5,%6,%7}, {%8,%9}, {%0,%1,%2,%3};"
                : "+f"(acc[nt][0]), "+f"(acc[nt][1]), "+f"(acc[nt][2]), "+f"(acc[nt][3])
                : "r"(a0), "r"(a1), "r"(a2), "r"(a3), "r"(bb0), "r"(bb1));
        }
    }
    __syncthreads();   // done reading sX/sW1; sH may overwrite

#pragma unroll
    for (int nt = 0; nt < 8; nt++) {
        int c = (nhalf * 8 + nt) * 8 + 2 * tig;
        float b0 = bf1[c], b1 = bf1[c + 1];
        *(__half2*)&sH[rowA * HSP + c] =
            __floats2half2_rn(elu1(acc[nt][0] + b0), elu1(acc[nt][1] + b1));
        *(__half2*)&sH[(rowA + 8) * HSP + c] =
            __floats2half2_rn(elu1(acc[nt][2] + b0), elu1(acc[nt][3] + b1));
    }
    __syncthreads();

    for (int j = 0; j < 8; j++) {
        int r = wid * 8 + j;
        int node = m0 + r;
        if (node >= n) continue;
        int k0 = lane * 4;
        float2 f0 = __half22float2(*(const __half2*)&sH[r * HSP + k0]);
        float2 f1 = __half22float2(*(const __half2*)&sH[r * HSP + k0 + 2]);
        float a[NCLS];
#pragma unroll
        for (int c = 0; c < NCLS; c++) {
            const float* wr = &sWf2[c * HH + k0];
            a[c] = f0.x * wr[0] + f0.y * wr[1] + f1.x * wr[2] + f1.y * wr[3];
        }
#pragma unroll
        for (int off = 16; off > 0; off >>= 1) {
#pragma unroll
            for (int c = 0; c < NCLS; c++)
                a[c] += __shfl_xor_sync(0xFFFFFFFFu, a[c], off);
        }
        if (lane == 0) {
            float l[NCLS], mx = -1e30f;
#pragma unroll
            for (int c = 0; c < NCLS; c++) {
                l[c] = a[c] + sbf2[c];
                mx = fmaxf(mx, l[c]);
            }
            float se = 0.0f;
#pragma unroll
            for (int c = 0; c < NCLS; c++) se += expf(l[c] - mx);
            float lse = mx + logf(se);
#pragma unroll
            for (int c = 0; c < NCLS; c++) out[(size_t)node * NCLS + c] = l[c] - lse;
        }
    }
}
#define FC12_SMEM ((64 * XFP + 128 * XFP) * 2)   // 27648 bytes

// ---------------- launcher ----------------
static cudaStream_t g_s_csr = nullptr;
static cudaEvent_t  g_ev_fork = nullptr;
static cudaEvent_t  g_ev_join = nullptr;

extern "C" void kernel_launch(void* const* d_in, const int* in_sizes, int n_in,
                              void* d_out, int out_size) {
    const float* x   = (const float*)d_in[0];
    const int*   ei  = (const int*)d_in[1];
    const float* ea  = (const float*)d_in[2];
    const float* W1a = (const float*)d_in[3];
    const float* b1a = (const float*)d_in[4];
    const float* W1b = (const float*)d_in[5];
    const float* W1c = (const float*)d_in[6];
    const float* b1c = (const float*)d_in[7];
    const float* W2a = (const float*)d_in[8];
    const float* b2a = (const float*)d_in[9];
    const float* W2b = (const float*)d_in[10];
    const float* W2c = (const float*)d_in[11];
    const float* b2c = (const float*)d_in[12];
    const float* Wf1 = (const float*)d_in[13];
    const float* bf1 = (const float*)d_in[14];
    const float* Wf2 = (const float*)d_in[15];
    const float* bf2 = (const float*)d_in[16];
    float* out = (float*)d_out;

    const int* src = ei;
    const int* dst = ei + EE;

    __half *a1, *b1, *c1, *h1, *gG, *h2;
    float *wsv;
    cudaGetSymbolAddress((void**)&a1, g_a1);
    cudaGetSymbolAddress((void**)&b1, g_b1);
    cudaGetSymbolAddress((void**)&c1, g_c1);
    cudaGetSymbolAddress((void**)&h1, g_h1);
    cudaGetSymbolAddress((void**)&gG, g_g);
    cudaGetSymbolAddress((void**)&h2, g_h2);
    cudaGetSymbolAddress((void**)&wsv, g_wsum);

    if (g_s_csr == nullptr) {
        cudaStreamCreateWithFlags(&g_s_csr, cudaStreamNonBlocking);
        cudaEventCreateWithFlags(&g_ev_fork, cudaEventDisableTiming);
        cudaEventCreateWithFlags(&g_ev_join, cudaEventDisableTiming);
        cudaFuncSetAttribute(gemm1_tc_kernel,
                             cudaFuncAttributeMaxDynamicSharedMemorySize, GEMM1_SMEM);
        cudaFuncSetAttribute(fc12_kernel,
                             cudaFuncAttributeMaxDynamicSharedMemorySize, FC12_SMEM);
    }

    // Fork: scatter-only CSR build on side stream (g_cur pre-zeroed by previous run)
    cudaEventRecord(g_ev_fork, 0);
    cudaStreamWaitEvent(g_s_csr, g_ev_fork, 0);

    scatter_kernel<<<(EE / 4 + 255) / 256, 256, 0, g_s_csr>>>(
        (const int4*)src, (const int4*)dst, (const float4*)ea);
    cudaEventRecord(g_ev_join, g_s_csr);

    // conv1: W prep + tensor-core GEMM on main stream
    prep_w_kernel<<<(PREPW_TOTAL + 255) / 256, 256>>>(W1a, W1b, W1c, W2a, W2b, W2c, Wf1);
    gemm1_tc_kernel<<<(NN + 63) / 64, 256, GEMM1_SMEM>>>(x, b1a, b1c, a1, b1, c1, NN);

    cudaStreamWaitEvent(0, g_ev_join, 0);

    gather32_kernel<<<(NN + G32_NPB - 1) / G32_NPB, 256>>>((const __half2*)a1, (const __half2*)b1,
                                                           (const __half2*)c1, h1, wsv, NN);
    gatherg_kernel<<<(NN + G32_NPB - 1) / G32_NPB, 256>>>((const __half2*)h1, gG, NN);
    gemm2f_kernel<<<(NN + 63) / 64, 256>>>(h1, gG, wsv, b2a, b2c, h2, NN);
    fc12_kernel<<<(NN + 63) / 64, 256, FC12_SMEM>>>(h2, bf1, Wf2, bf2, out, NN);
}

// round 16
// speedup vs baseline: 1.0547x; 1.0547x over previous
#include <cuda_runtime.h>
#include <cuda_fp16.h>
#include <math.h>

#define NN 100000
#define EE 3200000
#define FIN 256
#define CC1 32
#define CC2 64
#define HH 128
#define NCLS 10
#define CAP 128            // bucket capacity per node (max observed degree ~75)

typedef unsigned long long ull;

// ---------------- scratch (__device__ globals; no allocation allowed) ----------------
__device__ int    g_cur[NN];                 // zero-init; self-reset by gatherg each run
__device__ ull    g_csr[(size_t)NN * CAP];   // packed (w<<32 | src*64), bucketed
__device__ __half g_wcat1[96 * FIN];         // conv1 WcatT[n][k] fp16
__device__ __half g_wcat2f[CC2 * 96];        // fused conv2 W[n][k]: [W2a | W2c | -W2b] fp16
__device__ __half g_wf1t[HH * CC2];          // fc1 WT[n][k] fp16

__device__ __half g_a1[NN * CC1];    // conv1 lin1 table, fp16 (64B rows)
__device__ __half g_b1[NN * CC1];    // conv1 lin2 table, fp16
__device__ __half g_c1[NN * CC1];    // conv1 lin3 table, fp16
__device__ __half g_h1[NN * CC1];    // conv1 output, fp16 (64B rows)
__device__ float  g_wsum[NN];        // per-node sum of edge weights
__device__ __half g_g[NN * CC1];     // G = sum_e w*h1[src], fp16
__device__ __half g_h2[NN * CC2];    // conv2 output, fp16

__device__ __forceinline__ float elu1(float v) {
    return v > 0.0f ? v : expm1f(v);
}

// ---------------- bucketed CSR build: scatter only (g_cur self-resets) ----------------
__device__ __forceinline__ void scat1(int d, int s, float w) {
    int p = atomicAdd(&g_cur[d], 1);
    if (p < CAP) {
        ull pack = ((ull)(unsigned int)__float_as_int(w) << 32) | (unsigned int)(s * 64);
        g_csr[(size_t)d * CAP + p] = pack;
    }
}

__global__ void scatter_kernel(const int4* __restrict__ src4, const int4* __restrict__ dst4,
                               const float4* __restrict__ ew4) {
    int e4 = blockIdx.x * blockDim.x + threadIdx.x;
    if (e4 < EE / 4) {
        int4   s = src4[e4];
        int4   d = dst4[e4];
        float4 w = ew4[e4];
        scat1(d.x, s.x, w.x);
        scat1(d.y, s.y, w.y);
        scat1(d.z, s.z, w.z);
        scat1(d.w, s.w, w.w);
    }
}

// ---------------- W prep ----------------
#define PREPW_TOTAL (96 * FIN + CC2 * 96 + HH * CC2)
__global__ void prep_w_kernel(const float* __restrict__ W1a, const float* __restrict__ W1b,
                              const float* __restrict__ W1c,
                              const float* __restrict__ W2a, const float* __restrict__ W2b,
                              const float* __restrict__ W2c,
                              const float* __restrict__ Wf1) {
    int idx = blockIdx.x * blockDim.x + threadIdx.x;
    if (idx < 96 * FIN) {
        int nn = idx / FIN, k = idx % FIN;
        float v = (nn < 32) ? W1a[k * 32 + nn]
                : (nn < 64) ? W1b[k * 32 + (nn - 32)]
                            : W1c[k * 32 + (nn - 64)];
        g_wcat1[idx] = __float2half(v);
    } else if (idx < 96 * FIN + CC2 * 96) {
        int j = idx - 96 * FIN;
        int nn = j / 96, k = j % 96;
        float v = (k < 32) ? W2a[k * 64 + nn]
                : (k < 64) ? W2c[(k - 32) * 64 + nn]
                           : -W2b[(k - 64) * 64 + nn];
        g_wcat2f[j] = __float2half(v);
    } else if (idx < PREPW_TOTAL) {
        int j = idx - 96 * FIN - CC2 * 96;
        int nn = j / CC2, k = j % CC2;
        g_wf1t[j] = __float2half(Wf1[k * HH + nn]);
    }
}

// ================= conv1 GEMM: HMMA, M=64 tile, warp-split N, K dbuf 64 =================
#define XP 72
#define GEMM1_SMEM ((2 * 64 * XP + 2 * 96 * XP) * 2)   // 46080 bytes
__global__ __launch_bounds__(256)
void gemm1_tc_kernel(const float* __restrict__ X,
                     const float* __restrict__ b0v, const float* __restrict__ b2v,
                     __half* __restrict__ outA, __half* __restrict__ outB,
                     __half* __restrict__ outC, int n) {
    extern __shared__ __half smem[];
    __half* sX = smem;                   // [2][64][XP]
    __half* sW = smem + 2 * 64 * XP;     // [2][96][XP]

    int tid = threadIdx.x;
    int wid = tid >> 5;
    int lane = tid & 31;
    int gid = lane >> 2;
    int tig = lane & 3;
    int mgrp = wid & 3;
    int nhalf = wid >> 2;
    int m0 = blockIdx.x * 64;

    auto loadX = [&](int buf, int kt) {
        __half* dst = sX + buf * 64 * XP;
#pragma unroll
        for (int i = tid; i < 64 * 16; i += 256) {
            int m = i >> 4, kq = i & 15;
            int gm = m0 + m;
            float4 v = make_float4(0.f, 0.f, 0.f, 0.f);
            if (gm < n) v = *(const float4*)&X[(size_t)gm * FIN + kt + kq * 4];
            *(__half2*)&dst[m * XP + kq * 4]     = __floats2half2_rn(v.x, v.y);
            *(__half2*)&dst[m * XP + kq * 4 + 2] = __floats2half2_rn(v.z, v.w);
        }
    };
    auto loadW = [&](int buf, int kt) {
        __half* dst = sW + buf * 96 * XP;
#pragma unroll
        for (int i = tid; i < 96 * 8; i += 256) {
            int nn = i >> 3, kq = i & 7;
            *(int4*)&dst[nn * XP + kq * 8] = *(const int4*)&g_wcat1[nn * FIN + kt + kq * 8];
        }
    };

    loadX(0, 0); loadW(0, 0);
    __syncthreads();

    float acc[6][4];
#pragma unroll
    for (int t = 0; t < 6; t++)
#pragma unroll
        for (int j = 0; j < 4; j++) acc[t][j] = 0.0f;

    int rowA = mgrp * 16 + gid;
#pragma unroll
    for (int c = 0; c < 4; c++) {
        int buf = c & 1;
        if (c < 3) { loadX(buf ^ 1, (c + 1) * 64); loadW(buf ^ 1, (c + 1) * 64); }
        const __half* bX = sX + buf * 64 * XP;
        const __half* bW = sW + buf * 96 * XP;
#pragma unroll
        for (int kt = 0; kt < 64; kt += 16) {
            unsigned a0 = *(const unsigned*)&bX[rowA * XP + kt + 2 * tig];
            unsigned a1 = *(const unsigned*)&bX[(rowA + 8) * XP + kt + 2 * tig];
            unsigned a2 = *(const unsigned*)&bX[rowA * XP + kt + 8 + 2 * tig];
            unsigned a3 = *(const unsigned*)&bX[(rowA + 8) * XP + kt + 8 + 2 * tig];
#pragma unroll
            for (int nt = 0; nt < 6; nt++) {
                int nn = nhalf * 48 + nt * 8 + gid;
                unsigned bb0 = *(const unsigned*)&bW[nn * XP + kt + 2 * tig];
                unsigned bb1 = *(const unsigned*)&bW[nn * XP + kt + 8 + 2 * tig];
                asm volatile(
                    "mma.sync.aligned.m16n8k16.row.col.f32.f16.f16.f32 "
                    "{%0,%1,%2,%3}, {%4,%5,%6,%7}, {%8,%9}, {%0,%1,%2,%3};"
                    : "+f"(acc[nt][0]), "+f"(acc[nt][1]), "+f"(acc[nt][2]), "+f"(acc[nt][3])
                    : "r"(a0), "r"(a1), "r"(a2), "r"(a3), "r"(bb0), "r"(bb1));
            }
        }
        __syncthreads();
    }

    int node0 = m0 + rowA;
    int node1 = node0 + 8;
#pragma unroll
    for (int nt = 0; nt < 6; nt++) {
        int c0 = nhalf * 48 + nt * 8 + 2 * tig;
        if (c0 < 32) {
            float ba0 = b0v[c0], ba1 = b0v[c0 + 1];
            if (node0 < n)
                *(__half2*)&outA[(size_t)node0 * 32 + c0] = __floats2half2_rn(acc[nt][0] + ba0, acc[nt][1] + ba1);
            if (node1 < n)
                *(__half2*)&outA[(size_t)node1 * 32 + c0] = __floats2half2_rn(acc[nt][2] + ba0, acc[nt][3] + ba1);
        } else if (c0 < 64) {
            int cc = c0 - 32;
            if (node0 < n)
                *(__half2*)&outB[(size_t)node0 * 32 + cc] = __floats2half2_rn(acc[nt][0], acc[nt][1]);
            if (node1 < n)
                *(__half2*)&outB[(size_t)node1 * 32 + cc] = __floats2half2_rn(acc[nt][2], acc[nt][3]);
        } else {
            int cc = c0 - 64;
            float bc0 = b2v[cc], bc1 = b2v[cc + 1];
            if (node0 < n)
                *(__half2*)&outC[(size_t)node0 * 32 + cc] = __floats2half2_rn(acc[nt][0] + bc0, acc[nt][1] + bc1);
            if (node1 < n)
                *(__half2*)&outC[(size_t)node1 * 32 + cc] = __floats2half2_rn(acc[nt][2] + bc0, acc[nt][3] + bc1);
        }
    }
}

// ---------------- gather32 (R14 form, byte-offset CSR): warp/node, even/odd halves ----------------
#define G32_NPB 8
__global__ __launch_bounds__(256)
void gather32_kernel(const __half* __restrict__ Atab, const __half2* __restrict__ Bh2,
                     const __half2* __restrict__ Ch2, __half* __restrict__ H,
                     float* __restrict__ wsv, int n) {
    __shared__ ull se[G32_NPB * CAP];
    __shared__ int scnt[G32_NPB];
    int base = blockIdx.x * G32_NPB;
    int tid = threadIdx.x;
    int wid = tid >> 5, lane = tid & 31;
    int sub = lane & 15, hf = lane >> 4;

    if (tid < G32_NPB) {
        int nd = base + tid;
        int c = (nd < n) ? g_cur[nd] : 0;
        scnt[tid] = c < CAP ? c : CAP;
    }
    __syncthreads();
    for (int i = tid; i < G32_NPB * CAP; i += 256) {
        int slot = i >> 7, off = i & (CAP - 1);
        if (off < scnt[slot]) se[i] = g_csr[(size_t)(base + slot) * CAP + off];
    }
    __syncthreads();

    int node = base + wid;
    if (node >= n) return;

    const char* Abase = (const char*)Atab + sub * 4;   // per-thread channel base
    int cnt = scnt[wid];
    const ull* eb = &se[wid * CAP];
    float ax = 0.0f, ay = 0.0f, wsum = 0.0f;
    int e = hf;
    for (; e + 14 < cnt; e += 16) {
        ull p[8];
#pragma unroll
        for (int j = 0; j < 8; j++) p[j] = eb[e + 2 * j];
        float w[8]; float2 f[8];
#pragma unroll
        for (int j = 0; j < 8; j++) {
            unsigned off = (unsigned int)p[j];
            w[j] = __uint_as_float((unsigned int)(p[j] >> 32));
            f[j] = __half22float2(*(const __half2*)(Abase + off));
        }
#pragma unroll
        for (int j = 0; j < 8; j++) {
            ax += w[j] * f[j].x;
            ay += w[j] * f[j].y;
            wsum += w[j];
        }
    }
    for (; e < cnt; e += 2) {
        ull p = eb[e];
        unsigned off = (unsigned int)p;
        float w = __uint_as_float((unsigned int)(p >> 32));
        float2 f = __half22float2(*(const __half2*)(Abase + off));
        ax += w * f.x; ay += w * f.y; wsum += w;
    }
    ax   += __shfl_xor_sync(0xFFFFFFFFu, ax, 16);
    ay   += __shfl_xor_sync(0xFFFFFFFFu, ay, 16);
    wsum += __shfl_xor_sync(0xFFFFFFFFu, wsum, 16);

    if (hf == 0) {
        float2 bv = __half22float2(Bh2[(size_t)node * 16 + sub]);
        float2 cv = __half22float2(Ch2[(size_t)node * 16 + sub]);
        __half2 o = __floats2half2_rn(elu1(ax - wsum * bv.x + cv.x),
                                      elu1(ay - wsum * bv.y + cv.y));
        *(__half2*)&H[(size_t)node * CC1 + 2 * sub] = o;
        if (sub == 0) wsv[node] = wsum;
    }
}

// ---------------- gatherg (R14 form, byte-offset CSR); resets g_cur ----------------
__global__ __launch_bounds__(256)
void gatherg_kernel(const __half* __restrict__ Htab, __half* __restrict__ G, int n) {
    __shared__ ull se[G32_NPB * CAP];
    __shared__ int scnt[G32_NPB];
    int base = blockIdx.x * G32_NPB;
    int tid = threadIdx.x;
    int wid = tid >> 5, lane = tid & 31;
    int sub = lane & 15, hf = lane >> 4;

    if (tid < G32_NPB) {
        int nd = base + tid;
        int c = (nd < n) ? g_cur[nd] : 0;
        scnt[tid] = c < CAP ? c : CAP;
    }
    __syncthreads();
    // self-reset counters for the next launch (deterministic; last consumer)
    if (tid < G32_NPB && base + tid < n) g_cur[base + tid] = 0;
    for (int i = tid; i < G32_NPB * CAP; i += 256) {
        int slot = i >> 7, off = i & (CAP - 1);
        if (off < scnt[slot]) se[i] = g_csr[(size_t)(base + slot) * CAP + off];
    }
    __syncthreads();

    int node = base + wid;
    if (node >= n) return;

    const char* Hbase = (const char*)Htab + sub * 4;
    int cnt = scnt[wid];
    const ull* eb = &se[wid * CAP];
    float ax = 0.0f, ay = 0.0f;
    int e = hf;
    for (; e + 14 < cnt; e += 16) {
        ull p[8];
#pragma unroll
        for (int j = 0; j < 8; j++) p[j] = eb[e + 2 * j];
        float w[8]; float2 f[8];
#pragma unroll
        for (int j = 0; j < 8; j++) {
            unsigned off = (unsigned int)p[j];
            w[j] = __uint_as_float((unsigned int)(p[j] >> 32));
            f[j] = __half22float2(*(const __half2*)(Hbase + off));
        }
#pragma unroll
        for (int j = 0; j < 8; j++) {
            ax += w[j] * f[j].x;
            ay += w[j] * f[j].y;
        }
    }
    for (; e < cnt; e += 2) {
        ull p = eb[e];
        unsigned off = (unsigned int)p;
        float w = __uint_as_float((unsigned int)(p >> 32));
        float2 f = __half22float2(*(const __half2*)(Hbase + off));
        ax += w * f.x; ay += w * f.y;
    }
    ax += __shfl_xor_sync(0xFFFFFFFFu, ax, 16);
    ay += __shfl_xor_sync(0xFFFFFFFFu, ay, 16);

    if (hf == 0)
        *(__half2*)&G[(size_t)node * CC1 + 2 * sub] = __floats2half2_rn(ax, ay);
}

// ================= fused conv2 GEMM: h2 = elu([G,h1,ws*h1] @ Wcat + ws*b2a + b2c) =================
#define AP 104   // K=96 + pad
__global__ __launch_bounds__(256)
void gemm2f_kernel(const __half* __restrict__ h1, const __half* __restrict__ G,
                   const float* __restrict__ wsv,
                   const float* __restrict__ b2a, const float* __restrict__ b2c,
                   __half* __restrict__ h2, int n) {
    __shared__ __half sA[64 * AP];
    __shared__ __half sW[64 * AP];

    int tid = threadIdx.x;
    int wid = tid >> 5;
    int lane = tid & 31;
    int gid = lane >> 2;
    int tig = lane & 3;
    int mgrp = wid & 3;
    int nhalf = wid >> 2;
    int m0 = blockIdx.x * 64;

    // build A rows: [G(0..31) | h1(32..63) | ws*h1(64..95)]
    for (int i = tid; i < 64 * 12; i += 256) {
        int m = i / 12, kq = i % 12;
        int gm = m0 + m;
        if (kq < 4) {
            int4 v = make_int4(0, 0, 0, 0);
            if (gm < n) v = *(const int4*)&G[(size_t)gm * 32 + kq * 8];
            *(int4*)&sA[m * AP + kq * 8] = v;
        } else if (kq < 8) {
            int4 v = make_int4(0, 0, 0, 0);
            if (gm < n) v = *(const int4*)&h1[(size_t)gm * 32 + (kq - 4) * 8];
            *(int4*)&sA[m * AP + 32 + (kq - 4) * 8] = v;
        } else {
            __half2 hv[4] = {__half2{}, __half2{}, __half2{}, __half2{}};
            if (gm < n) {
                float ws = wsv[gm];
#pragma unroll
                for (int q = 0; q < 4; q++) {
                    float2 f = __half22float2(*(const __half2*)&h1[(size_t)gm * 32 + (kq - 8) * 8 + 2 * q]);
                    hv[q] = __floats2half2_rn(ws * f.x, ws * f.y);
                }
            }
            *(int4*)&sA[m * AP + 64 + (kq - 8) * 8] = *(int4*)hv;
        }
    }
    for (int i = tid; i < 64 * 12; i += 256) {
        int nn = i / 12, kq = i % 12;
        *(int4*)&sW[nn * AP + kq * 8] = *(const int4*)&g_wcat2f[nn * 96 + kq * 8];
    }
    __syncthreads();

    float acc[4][4];
#pragma unroll
    for (int t = 0; t < 4; t++)
#pragma unroll
        for (int j = 0; j < 4; j++) acc[t][j] = 0.0f;

    int rowA = mgrp * 16 + gid;
#pragma unroll
    for (int kt = 0; kt < 96; kt += 16) {
        unsigned a0 = *(const unsigned*)&sA[rowA * AP + kt + 2 * tig];
        unsigned a1 = *(const unsigned*)&sA[(rowA + 8) * AP + kt + 2 * tig];
        unsigned a2 = *(const unsigned*)&sA[rowA * AP + kt + 8 + 2 * tig];
        unsigned a3 = *(const unsigned*)&sA[(rowA + 8) * AP + kt + 8 + 2 * tig];
#pragma unroll
        for (int nt = 0; nt < 4; nt++) {
            int nn = nhalf * 32 + nt * 8 + gid;
            unsigned bb0 = *(const unsigned*)&sW[nn * AP + kt + 2 * tig];
            unsigned bb1 = *(const unsigned*)&sW[nn * AP + kt + 8 + 2 * tig];
            asm volatile(
                "mma.sync.aligned.m16n8k16.row.col.f32.f16.f16.f32 "
                "{%0,%1,%2,%3}, {%4,%5,%6,%7}, {%8,%9}, {%0,%1,%2,%3};"
                : "+f"(acc[nt][0]), "+f"(acc[nt][1]), "+f"(acc[nt][2]), "+f"(acc[nt][3])
                : "r"(a0), "r"(a1), "r"(a2), "r"(a3), "r"(bb0), "r"(bb1));
        }
    }

    int node0 = m0 + rowA;
    int node1 = node0 + 8;
    float ws0 = (node0 < n) ? wsv[node0] : 0.0f;
    float ws1 = (node1 < n) ? wsv[node1] : 0.0f;
#pragma unroll
    for (int nt = 0; nt < 4; nt++) {
        int c = nhalf * 32 + nt * 8 + 2 * tig;
        float ba0 = b2a[c], ba1 = b2a[c + 1];
        float bc0 = b2c[c], bc1 = b2c[c + 1];
        if (node0 < n)
            *(__half2*)&h2[(size_t)node0 * 64 + c] =
                __floats2half2_rn(elu1(acc[nt][0] + ws0 * ba0 + bc0),
                                  elu1(acc[nt][1] + ws0 * ba1 + bc1));
        if (node1 < n)
            *(__half2*)&h2[(size_t)node1 * 64 + c] =
                __floats2half2_rn(elu1(acc[nt][2] + ws1 * ba0 + bc0),
                                  elu1(acc[nt][3] + ws1 * ba1 + bc1));
    }
}

// ================= fused fc1+fc2+log_softmax =================
#define XFP 72
#define HSP 136
__global__ __launch_bounds__(256)
void fc12_kernel(const __half* __restrict__ Xh, const float* __restrict__ bf1,
                 const float* __restrict__ Wf2, const float* __restrict__ bf2,
                 float* __restrict__ out, int n) {
    extern __shared__ __half dsm[];
    __half* sX  = dsm;               // [64][XFP]
    __half* sW1 = dsm + 64 * XFP;    // [128][XFP]
    __half* sH  = dsm;               // [64][HSP] alias (used after phase A)
    __shared__ float sWf2[NCLS * HH];
    __shared__ float sbf2[NCLS];

    int tid = threadIdx.x;
    int wid = tid >> 5;
    int lane = tid & 31;
    int gid = lane >> 2;
    int tig = lane & 3;
    int mgrp = wid & 3;
    int nhalf = wid >> 2;
    int m0 = blockIdx.x * 64;

    for (int i = tid; i < 64 * 8; i += 256) {
        int m = i >> 3, kq = i & 7;
        int gm = m0 + m;
        int4 v = make_int4(0, 0, 0, 0);
        if (gm < n) v = *(const int4*)&Xh[(size_t)gm * 64 + kq * 8];
        *(int4*)&sX[m * XFP + kq * 8] = v;
    }
    for (int i = tid; i < 128 * 8; i += 256) {
        int nn = i >> 3, kq = i & 7;
        *(int4*)&sW1[nn * XFP + kq * 8] = *(const int4*)&g_wf1t[nn * 64 + kq * 8];
    }
    for (int i = tid; i < HH * NCLS; i += 256) {
        int k = i / NCLS, c = i % NCLS;
        sWf2[c * HH + k] = Wf2[i];
    }
    if (tid < NCLS) sbf2[tid] = bf2[tid];
    __syncthreads();

    float acc[8][4];
#pragma unroll
    for (int t = 0; t < 8; t++)
#pragma unroll
        for (int j = 0; j < 4; j++) acc[t][j] = 0.0f;

    int rowA = mgrp * 16 + gid;
#pragma unroll
    for (int kt = 0; kt < 64; kt += 16) {
        unsigned a0 = *(const unsigned*)&sX[rowA * XFP + kt + 2 * tig];
        unsigned a1 = *(const unsigned*)&sX[(rowA + 8) * XFP + kt + 2 * tig];
        unsigned a2 = *(const unsigned*)&sX[rowA * XFP + kt + 8 + 2 * tig];
        unsigned a3 = *(const unsigned*)&sX[(rowA + 8) * XFP + kt + 8 + 2 * tig];
#pragma unroll
        for (int nt = 0; nt < 8; nt++) {
            int nn = (nhalf * 8 + nt) * 8 + gid;
            unsigned bb0 = *(const unsigned*)&sW1[nn * XFP + kt + 2 * tig];
            unsigned bb1 = *(const unsigned*)&sW1[nn * XFP + kt + 8 + 2 * tig];
            asm volatile(
                "mma.sync.aligned.m16n8k16.row.col.f32.f16.f16.f32 "
                "{%0,%1,%2,%3}, {%4,%5,%6,%7}, {%8,%9}, {%0,%1,%2,%3};"
                : "+f"(acc[nt][0]), "+f"(acc[nt][1]), "+f"(acc[nt][2]), "+f"(acc[nt][3])
                : "r"(a0), "r"(a1), "r"(a2), "r"(a3), "r"(bb0), "r"(bb1));
        }
    }
    __syncthreads();   // done reading sX/sW1; sH may overwrite

#pragma unroll
    for (int nt = 0; nt < 8; nt++) {
        int c = (nhalf * 8 + nt) * 8 + 2 * tig;
        float b0 = bf1[c], b1 = bf1[c + 1];
        *(__half2*)&sH[rowA * HSP + c] =
            __floats2half2_rn(elu1(acc[nt][0] + b0), elu1(acc[nt][1] + b1));
        *(__half2*)&sH[(rowA + 8) * HSP + c] =
            __floats2half2_rn(elu1(acc[nt][2] + b0), elu1(acc[nt][3] + b1));
    }
    __syncthreads();

    for (int j = 0; j < 8; j++) {
        int r = wid * 8 + j;
        int node = m0 + r;
        if (node >= n) continue;
        int k0 = lane * 4;
        float2 f0 = __half22float2(*(const __half2*)&sH[r * HSP + k0]);
        float2 f1 = __half22float2(*(const __half2*)&sH[r * HSP + k0 + 2]);
        float a[NCLS];
#pragma unroll
        for (int c = 0; c < NCLS; c++) {
            const float* wr = &sWf2[c * HH + k0];
            a[c] = f0.x * wr[0] + f0.y * wr[1] + f1.x * wr[2] + f1.y * wr[3];
        }
#pragma unroll
        for (int off = 16; off > 0; off >>= 1) {
#pragma unroll
            for (int c = 0; c < NCLS; c++)
                a[c] += __shfl_xor_sync(0xFFFFFFFFu, a[c], off);
        }
        if (lane == 0) {
            float l[NCLS], mx = -1e30f;
#pragma unroll
            for (int c = 0; c < NCLS; c++) {
                l[c] = a[c] + sbf2[c];
                mx = fmaxf(mx, l[c]);
            }
            float se = 0.0f;
#pragma unroll
            for (int c = 0; c < NCLS; c++) se += expf(l[c] - mx);
            float lse = mx + logf(se);
#pragma unroll
            for (int c = 0; c < NCLS; c++) out[(size_t)node * NCLS + c] = l[c] - lse;
        }
    }
}
#define FC12_SMEM ((64 * XFP + 128 * XFP) * 2)   // 27648 bytes

// ---------------- launcher ----------------
static cudaStream_t g_s_csr = nullptr;
static cudaEvent_t  g_ev_fork = nullptr;
static cudaEvent_t  g_ev_join = nullptr;

extern "C" void kernel_launch(void* const* d_in, const int* in_sizes, int n_in,
                              void* d_out, int out_size) {
    const float* x   = (const float*)d_in[0];
    const int*   ei  = (const int*)d_in[1];
    const float* ea  = (const float*)d_in[2];
    const float* W1a = (const float*)d_in[3];
    const float* b1a = (const float*)d_in[4];
    const float* W1b = (const float*)d_in[5];
    const float* W1c = (const float*)d_in[6];
    const float* b1c = (const float*)d_in[7];
    const float* W2a = (const float*)d_in[8];
    const float* b2a = (const float*)d_in[9];
    const float* W2b = (const float*)d_in[10];
    const float* W2c = (const float*)d_in[11];
    const float* b2c = (const float*)d_in[12];
    const float* Wf1 = (const float*)d_in[13];
    const float* bf1 = (const float*)d_in[14];
    const float* Wf2 = (const float*)d_in[15];
    const float* bf2 = (const float*)d_in[16];
    float* out = (float*)d_out;

    const int* src = ei;
    const int* dst = ei + EE;

    __half *a1, *b1, *c1, *h1, *gG, *h2;
    float *wsv;
    cudaGetSymbolAddress((void**)&a1, g_a1);
    cudaGetSymbolAddress((void**)&b1, g_b1);
    cudaGetSymbolAddress((void**)&c1, g_c1);
    cudaGetSymbolAddress((void**)&h1, g_h1);
    cudaGetSymbolAddress((void**)&gG, g_g);
    cudaGetSymbolAddress((void**)&h2, g_h2);
    cudaGetSymbolAddress((void**)&wsv, g_wsum);

    if (g_s_csr == nullptr) {
        cudaStreamCreateWithFlags(&g_s_csr, cudaStreamNonBlocking);
        cudaEventCreateWithFlags(&g_ev_fork, cudaEventDisableTiming);
        cudaEventCreateWithFlags(&g_ev_join, cudaEventDisableTiming);
        cudaFuncSetAttribute(gemm1_tc_kernel,
                             cudaFuncAttributeMaxDynamicSharedMemorySize, GEMM1_SMEM);
        cudaFuncSetAttribute(fc12_kernel,
                             cudaFuncAttributeMaxDynamicSharedMemorySize, FC12_SMEM);
    }

    // Fork: scatter-only CSR build on side stream (g_cur pre-zeroed by previous run)
    cudaEventRecord(g_ev_fork, 0);
    cudaStreamWaitEvent(g_s_csr, g_ev_fork, 0);

    scatter_kernel<<<(EE / 4 + 255) / 256, 256, 0, g_s_csr>>>(
        (const int4*)src, (const int4*)dst, (const float4*)ea);
    cudaEventRecord(g_ev_join, g_s_csr);

    // conv1: W prep + tensor-core GEMM on main stream
    prep_w_kernel<<<(PREPW_TOTAL + 255) / 256, 256>>>(W1a, W1b, W1c, W2a, W2b, W2c, Wf1);
    gemm1_tc_kernel<<<(NN + 63) / 64, 256, GEMM1_SMEM>>>(x, b1a, b1c, a1, b1, c1, NN);

    cudaStreamWaitEvent(0, g_ev_join, 0);

    gather32_kernel<<<(NN + G32_NPB - 1) / G32_NPB, 256>>>(a1, (const __half2*)b1,
                                                           (const __half2*)c1, h1, wsv, NN);
    gatherg_kernel<<<(NN + G32_NPB - 1) / G32_NPB, 256>>>(h1, gG, NN);
    gemm2f_kernel<<<(NN + 63) / 64, 256>>>(h1, gG, wsv, b2a, b2c, h2, NN);
    fc12_kernel<<<(NN + 63) / 64, 256, FC12_SMEM>>>(h2, bf1, Wf2, bf2, out, NN);
}

// round 17
// speedup vs baseline: 1.0611x; 1.0061x over previous
#include <cuda_runtime.h>
#include <cuda_fp16.h>
#include <math.h>

#define NN 100000
#define EE 3200000
#define FIN 256
#define CC1 32
#define CC2 64
#define HH 128
#define NCLS 10
#define CAP 128            // bucket capacity per node (max observed degree ~75)

typedef unsigned long long ull;

// ---------------- scratch (__device__ globals; no allocation allowed) ----------------
__device__ int    g_cur[NN];                 // zero-init; self-reset by gatherg each run
__device__ ull    g_csr[(size_t)NN * CAP];   // packed (w<<32 | src*64), bucketed
__device__ __half g_wcat1[96 * FIN];         // conv1 WcatT[n][k] fp16
__device__ __half g_wcat2f[CC2 * 96];        // fused conv2 W[n][k]: [W2a | W2c | -W2b] fp16
__device__ __half g_wf1t[HH * CC2];          // fc1 WT[n][k] fp16

__device__ __half g_a1[NN * CC1];    // conv1 lin1 table, fp16 (64B rows)
__device__ __half g_b1[NN * CC1];    // conv1 lin2 table, fp16
__device__ __half g_c1[NN * CC1];    // conv1 lin3 table, fp16
__device__ __half g_h1[NN * CC1];    // conv1 output, fp16 (64B rows)
__device__ float  g_wsum[NN];        // per-node sum of edge weights
__device__ __half g_g[NN * CC1];     // G = sum_e w*h1[src], fp16
__device__ __half g_h2[NN * CC2];    // conv2 output, fp16

__device__ __forceinline__ float elu1(float v) {
    return v > 0.0f ? v : expm1f(v);
}

__device__ __forceinline__ __half2 h2bits(unsigned u) {
    __half2 h;
    *(unsigned*)&h = u;
    return h;
}

// ---------------- bucketed CSR build: scatter only (g_cur self-resets) ----------------
__device__ __forceinline__ void scat1(int d, int s, float w) {
    int p = atomicAdd(&g_cur[d], 1);
    if (p < CAP) {
        ull pack = ((ull)(unsigned int)__float_as_int(w) << 32) | (unsigned int)(s * 64);
        g_csr[(size_t)d * CAP + p] = pack;
    }
}

__global__ void scatter_kernel(const int4* __restrict__ src4, const int4* __restrict__ dst4,
                               const float4* __restrict__ ew4) {
    int e4 = blockIdx.x * blockDim.x + threadIdx.x;
    if (e4 < EE / 4) {
        int4   s = src4[e4];
        int4   d = dst4[e4];
        float4 w = ew4[e4];
        scat1(d.x, s.x, w.x);
        scat1(d.y, s.y, w.y);
        scat1(d.z, s.z, w.z);
        scat1(d.w, s.w, w.w);
    }
}

// ---------------- W prep ----------------
#define PREPW_TOTAL (96 * FIN + CC2 * 96 + HH * CC2)
__global__ void prep_w_kernel(const float* __restrict__ W1a, const float* __restrict__ W1b,
                              const float* __restrict__ W1c,
                              const float* __restrict__ W2a, const float* __restrict__ W2b,
                              const float* __restrict__ W2c,
                              const float* __restrict__ Wf1) {
    int idx = blockIdx.x * blockDim.x + threadIdx.x;
    if (idx < 96 * FIN) {
        int nn = idx / FIN, k = idx % FIN;
        float v = (nn < 32) ? W1a[k * 32 + nn]
                : (nn < 64) ? W1b[k * 32 + (nn - 32)]
                            : W1c[k * 32 + (nn - 64)];
        g_wcat1[idx] = __float2half(v);
    } else if (idx < 96 * FIN + CC2 * 96) {
        int j = idx - 96 * FIN;
        int nn = j / 96, k = j % 96;
        float v = (k < 32) ? W2a[k * 64 + nn]
                : (k < 64) ? W2c[(k - 32) * 64 + nn]
                           : -W2b[(k - 64) * 64 + nn];
        g_wcat2f[j] = __float2half(v);
    } else if (idx < PREPW_TOTAL) {
        int j = idx - 96 * FIN - CC2 * 96;
        int nn = j / CC2, k = j % CC2;
        g_wf1t[j] = __float2half(Wf1[k * HH + nn]);
    }
}

// ================= conv1 GEMM: HMMA, M=64 tile, warp-split N, K dbuf 64 =================
#define XP 72
#define GEMM1_SMEM ((2 * 64 * XP + 2 * 96 * XP) * 2)   // 46080 bytes
__global__ __launch_bounds__(256)
void gemm1_tc_kernel(const float* __restrict__ X,
                     const float* __restrict__ b0v, const float* __restrict__ b2v,
                     __half* __restrict__ outA, __half* __restrict__ outB,
                     __half* __restrict__ outC, int n) {
    extern __shared__ __half smem[];
    __half* sX = smem;                   // [2][64][XP]
    __half* sW = smem + 2 * 64 * XP;     // [2][96][XP]

    int tid = threadIdx.x;
    int wid = tid >> 5;
    int lane = tid & 31;
    int gid = lane >> 2;
    int tig = lane & 3;
    int mgrp = wid & 3;
    int nhalf = wid >> 2;
    int m0 = blockIdx.x * 64;

    auto loadX = [&](int buf, int kt) {
        __half* dst = sX + buf * 64 * XP;
#pragma unroll
        for (int i = tid; i < 64 * 16; i += 256) {
            int m = i >> 4, kq = i & 15;
            int gm = m0 + m;
            float4 v = make_float4(0.f, 0.f, 0.f, 0.f);
            if (gm < n) v = *(const float4*)&X[(size_t)gm * FIN + kt + kq * 4];
            *(__half2*)&dst[m * XP + kq * 4]     = __floats2half2_rn(v.x, v.y);
            *(__half2*)&dst[m * XP + kq * 4 + 2] = __floats2half2_rn(v.z, v.w);
        }
    };
    auto loadW = [&](int buf, int kt) {
        __half* dst = sW + buf * 96 * XP;
#pragma unroll
        for (int i = tid; i < 96 * 8; i += 256) {
            int nn = i >> 3, kq = i & 7;
            *(int4*)&dst[nn * XP + kq * 8] = *(const int4*)&g_wcat1[nn * FIN + kt + kq * 8];
        }
    };

    loadX(0, 0); loadW(0, 0);
    __syncthreads();

    float acc[6][4];
#pragma unroll
    for (int t = 0; t < 6; t++)
#pragma unroll
        for (int j = 0; j < 4; j++) acc[t][j] = 0.0f;

    int rowA = mgrp * 16 + gid;
#pragma unroll
    for (int c = 0; c < 4; c++) {
        int buf = c & 1;
        if (c < 3) { loadX(buf ^ 1, (c + 1) * 64); loadW(buf ^ 1, (c + 1) * 64); }
        const __half* bX = sX + buf * 64 * XP;
        const __half* bW = sW + buf * 96 * XP;
#pragma unroll
        for (int kt = 0; kt < 64; kt += 16) {
            unsigned a0 = *(const unsigned*)&bX[rowA * XP + kt + 2 * tig];
            unsigned a1 = *(const unsigned*)&bX[(rowA + 8) * XP + kt + 2 * tig];
            unsigned a2 = *(const unsigned*)&bX[rowA * XP + kt + 8 + 2 * tig];
            unsigned a3 = *(const unsigned*)&bX[(rowA + 8) * XP + kt + 8 + 2 * tig];
#pragma unroll
            for (int nt = 0; nt < 6; nt++) {
                int nn = nhalf * 48 + nt * 8 + gid;
                unsigned bb0 = *(const unsigned*)&bW[nn * XP + kt + 2 * tig];
                unsigned bb1 = *(const unsigned*)&bW[nn * XP + kt + 8 + 2 * tig];
                asm volatile(
                    "mma.sync.aligned.m16n8k16.row.col.f32.f16.f16.f32 "
                    "{%0,%1,%2,%3}, {%4,%5,%6,%7}, {%8,%9}, {%0,%1,%2,%3};"
                    : "+f"(acc[nt][0]), "+f"(acc[nt][1]), "+f"(acc[nt][2]), "+f"(acc[nt][3])
                    : "r"(a0), "r"(a1), "r"(a2), "r"(a3), "r"(bb0), "r"(bb1));
            }
        }
        __syncthreads();
    }

    int node0 = m0 + rowA;
    int node1 = node0 + 8;
#pragma unroll
    for (int nt = 0; nt < 6; nt++) {
        int c0 = nhalf * 48 + nt * 8 + 2 * tig;
        if (c0 < 32) {
            float ba0 = b0v[c0], ba1 = b0v[c0 + 1];
            if (node0 < n)
                *(__half2*)&outA[(size_t)node0 * 32 + c0] = __floats2half2_rn(acc[nt][0] + ba0, acc[nt][1] + ba1);
            if (node1 < n)
                *(__half2*)&outA[(size_t)node1 * 32 + c0] = __floats2half2_rn(acc[nt][2] + ba0, acc[nt][3] + ba1);
        } else if (c0 < 64) {
            int cc = c0 - 32;
            if (node0 < n)
                *(__half2*)&outB[(size_t)node0 * 32 + cc] = __floats2half2_rn(acc[nt][0], acc[nt][1]);
            if (node1 < n)
                *(__half2*)&outB[(size_t)node1 * 32 + cc] = __floats2half2_rn(acc[nt][2], acc[nt][3]);
        } else {
            int cc = c0 - 64;
            float bc0 = b2v[cc], bc1 = b2v[cc + 1];
            if (node0 < n)
                *(__half2*)&outC[(size_t)node0 * 32 + cc] = __floats2half2_rn(acc[nt][0] + bc0, acc[nt][1] + bc1);
            if (node1 < n)
                *(__half2*)&outC[(size_t)node1 * 32 + cc] = __floats2half2_rn(acc[nt][2] + bc0, acc[nt][3] + bc1);
        }
    }
}

// ---------------- gather32: warp/node, 4 edge-groups x 8 channel-quad lanes ----------------
#define G32_NPB 8
__global__ __launch_bounds__(256)
void gather32_kernel(const __half* __restrict__ Atab, const __half* __restrict__ Btab,
                     const __half* __restrict__ Ctab, __half* __restrict__ H,
                     float* __restrict__ wsv, int n) {
    __shared__ ull se[G32_NPB * CAP];
    __shared__ int scnt[G32_NPB];
    int base = blockIdx.x * G32_NPB;
    int tid = threadIdx.x;
    int wid = tid >> 5, lane = tid & 31;
    int grp = lane >> 3;     // edge group 0..3
    int q   = lane & 7;      // channel quad (4 ch = 8 bytes)

    if (tid < G32_NPB) {
        int nd = base + tid;
        int c = (nd < n) ? g_cur[nd] : 0;
        scnt[tid] = c < CAP ? c : CAP;
    }
    __syncthreads();
    for (int i = tid; i < G32_NPB * CAP; i += 256) {
        int slot = i >> 7, off = i & (CAP - 1);
        if (off < scnt[slot]) se[i] = g_csr[(size_t)(base + slot) * CAP + off];
    }
    __syncthreads();

    int node = base + wid;
    if (node >= n) return;

    const char* Abase = (const char*)Atab + q * 8;   // per-thread 4-channel base
    int cnt = scnt[wid];
    const ull* eb = &se[wid * CAP];
    float a0 = 0.f, a1 = 0.f, a2 = 0.f, a3 = 0.f, wsum = 0.f;
    int e = grp;
    for (; e + 28 < cnt; e += 32) {
        ull p[8];
#pragma unroll
        for (int j = 0; j < 8; j++) p[j] = eb[e + 4 * j];
        uint2 v[8];
#pragma unroll
        for (int j = 0; j < 8; j++)
            v[j] = *(const uint2*)(Abase + (unsigned int)p[j]);
#pragma unroll
        for (int j = 0; j < 8; j++) {
            float w = __uint_as_float((unsigned int)(p[j] >> 32));
            float2 f0 = __half22float2(h2bits(v[j].x));
            float2 f1 = __half22float2(h2bits(v[j].y));
            a0 += w * f0.x; a1 += w * f0.y;
            a2 += w * f1.x; a3 += w * f1.y;
            wsum += w;
        }
    }
    for (; e < cnt; e += 4) {
        ull p = eb[e];
        uint2 v = *(const uint2*)(Abase + (unsigned int)p);
        float w = __uint_as_float((unsigned int)(p >> 32));
        float2 f0 = __half22float2(h2bits(v.x));
        float2 f1 = __half22float2(h2bits(v.y));
        a0 += w * f0.x; a1 += w * f0.y;
        a2 += w * f1.x; a3 += w * f1.y;
        wsum += w;
    }
    // reduce across the 4 edge groups (lanes differing in bits 3,4)
#pragma unroll
    for (int mask = 8; mask <= 16; mask <<= 1) {
        a0 += __shfl_xor_sync(0xFFFFFFFFu, a0, mask);
        a1 += __shfl_xor_sync(0xFFFFFFFFu, a1, mask);
        a2 += __shfl_xor_sync(0xFFFFFFFFu, a2, mask);
        a3 += __shfl_xor_sync(0xFFFFFFFFu, a3, mask);
        wsum += __shfl_xor_sync(0xFFFFFFFFu, wsum, mask);
    }

    if (grp == 0) {
        uint2 bb = *(const uint2*)((const char*)Btab + (size_t)node * 64 + q * 8);
        uint2 cc = *(const uint2*)((const char*)Ctab + (size_t)node * 64 + q * 8);
        float2 b0 = __half22float2(h2bits(bb.x));
        float2 b1 = __half22float2(h2bits(bb.y));
        float2 c0 = __half22float2(h2bits(cc.x));
        float2 c1 = __half22float2(h2bits(cc.y));
        __half2 o0 = __floats2half2_rn(elu1(a0 - wsum * b0.x + c0.x),
                                       elu1(a1 - wsum * b0.y + c0.y));
        __half2 o1 = __floats2half2_rn(elu1(a2 - wsum * b1.x + c1.x),
                                       elu1(a3 - wsum * b1.y + c1.y));
        uint2 ov;
        ov.x = *(unsigned*)&o0;
        ov.y = *(unsigned*)&o1;
        *(uint2*)((char*)H + (size_t)node * 64 + q * 8) = ov;
        if (q == 0) wsv[node] = wsum;
    }
}

// ---------------- gatherg: same structure; resets g_cur ----------------
__global__ __launch_bounds__(256)
void gatherg_kernel(const __half* __restrict__ Htab, __half* __restrict__ G, int n) {
    __shared__ ull se[G32_NPB * CAP];
    __shared__ int scnt[G32_NPB];
    int base = blockIdx.x * G32_NPB;
    int tid = threadIdx.x;
    int wid = tid >> 5, lane = tid & 31;
    int grp = lane >> 3;
    int q   = lane & 7;

    if (tid < G32_NPB) {
        int nd = base + tid;
        int c = (nd < n) ? g_cur[nd] : 0;
        scnt[tid] = c < CAP ? c : CAP;
    }
    __syncthreads();
    // self-reset counters for the next launch (deterministic; last consumer)
    if (tid < G32_NPB && base + tid < n) g_cur[base + tid] = 0;
    for (int i = tid; i < G32_NPB * CAP; i += 256) {
        int slot = i >> 7, off = i & (CAP - 1);
        if (off < scnt[slot]) se[i] = g_csr[(size_t)(base + slot) * CAP + off];
    }
    __syncthreads();

    int node = base + wid;
    if (node >= n) return;

    const char* Hbase = (const char*)Htab + q * 8;
    int cnt = scnt[wid];
    const ull* eb = &se[wid * CAP];
    float a0 = 0.f, a1 = 0.f, a2 = 0.f, a3 = 0.f;
    int e = grp;
    for (; e + 28 < cnt; e += 32) {
        ull p[8];
#pragma unroll
        for (int j = 0; j < 8; j++) p[j] = eb[e + 4 * j];
        uint2 v[8];
#pragma unroll
        for (int j = 0; j < 8; j++)
            v[j] = *(const uint2*)(Hbase + (unsigned int)p[j]);
#pragma unroll
        for (int j = 0; j < 8; j++) {
            float w = __uint_as_float((unsigned int)(p[j] >> 32));
            float2 f0 = __half22float2(h2bits(v[j].x));
            float2 f1 = __half22float2(h2bits(v[j].y));
            a0 += w * f0.x; a1 += w * f0.y;
            a2 += w * f1.x; a3 += w * f1.y;
        }
    }
    for (; e < cnt; e += 4) {
        ull p = eb[e];
        uint2 v = *(const uint2*)(Hbase + (unsigned int)p);
        float w = __uint_as_float((unsigned int)(p >> 32));
        float2 f0 = __half22float2(h2bits(v.x));
        float2 f1 = __half22float2(h2bits(v.y));
        a0 += w * f0.x; a1 += w * f0.y;
        a2 += w * f1.x; a3 += w * f1.y;
    }
#pragma unroll
    for (int mask = 8; mask <= 16; mask <<= 1) {
        a0 += __shfl_xor_sync(0xFFFFFFFFu, a0, mask);
        a1 += __shfl_xor_sync(0xFFFFFFFFu, a1, mask);
        a2 += __shfl_xor_sync(0xFFFFFFFFu, a2, mask);
        a3 += __shfl_xor_sync(0xFFFFFFFFu, a3, mask);
    }

    if (grp == 0) {
        __half2 o0 = __floats2half2_rn(a0, a1);
        __half2 o1 = __floats2half2_rn(a2, a3);
        uint2 ov;
        ov.x = *(unsigned*)&o0;
        ov.y = *(unsigned*)&o1;
        *(uint2*)((char*)G + (size_t)node * 64 + q * 8) = ov;
    }
}

// ================= fused conv2 GEMM: h2 = elu([G,h1,ws*h1] @ Wcat + ws*b2a + b2c) =================
#define AP 104   // K=96 + pad
__global__ __launch_bounds__(256)
void gemm2f_kernel(const __half* __restrict__ h1, const __half* __restrict__ G,
                   const float* __restrict__ wsv,
                   const float* __restrict__ b2a, const float* __restrict__ b2c,
                   __half* __restrict__ h2, int n) {
    __shared__ __half sA[64 * AP];
    __shared__ __half sW[64 * AP];

    int tid = threadIdx.x;
    int wid = tid >> 5;
    int lane = tid & 31;
    int gid = lane >> 2;
    int tig = lane & 3;
    int mgrp = wid & 3;
    int nhalf = wid >> 2;
    int m0 = blockIdx.x * 64;

    // build A rows: [G(0..31) | h1(32..63) | ws*h1(64..95)]
    for (int i = tid; i < 64 * 12; i += 256) {
        int m = i / 12, kq = i % 12;
        int gm = m0 + m;
        if (kq < 4) {
            int4 v = make_int4(0, 0, 0, 0);
            if (gm < n) v = *(const int4*)&G[(size_t)gm * 32 + kq * 8];
            *(int4*)&sA[m * AP + kq * 8] = v;
        } else if (kq < 8) {
            int4 v = make_int4(0, 0, 0, 0);
            if (gm < n) v = *(const int4*)&h1[(size_t)gm * 32 + (kq - 4) * 8];
            *(int4*)&sA[m * AP + 32 + (kq - 4) * 8] = v;
        } else {
            __half2 hv[4] = {__half2{}, __half2{}, __half2{}, __half2{}};
            if (gm < n) {
                float ws = wsv[gm];
#pragma unroll
                for (int qq = 0; qq < 4; qq++) {
                    float2 f = __half22float2(*(const __half2*)&h1[(size_t)gm * 32 + (kq - 8) * 8 + 2 * qq]);
                    hv[qq] = __floats2half2_rn(ws * f.x, ws * f.y);
                }
            }
            *(int4*)&sA[m * AP + 64 + (kq - 8) * 8] = *(int4*)hv;
        }
    }
    for (int i = tid; i < 64 * 12; i += 256) {
        int nn = i / 12, kq = i % 12;
        *(int4*)&sW[nn * AP + kq * 8] = *(const int4*)&g_wcat2f[nn * 96 + kq * 8];
    }
    __syncthreads();

    float acc[4][4];
#pragma unroll
    for (int t = 0; t < 4; t++)
#pragma unroll
        for (int j = 0; j < 4; j++) acc[t][j] = 0.0f;

    int rowA = mgrp * 16 + gid;
#pragma unroll
    for (int kt = 0; kt < 96; kt += 16) {
        unsigned a0 = *(const unsigned*)&sA[rowA * AP + kt + 2 * tig];
        unsigned a1 = *(const unsigned*)&sA[(rowA + 8) * AP + kt + 2 * tig];
        unsigned a2 = *(const unsigned*)&sA[rowA * AP + kt + 8 + 2 * tig];
        unsigned a3 = *(const unsigned*)&sA[(rowA + 8) * AP + kt + 8 + 2 * tig];
#pragma unroll
        for (int nt = 0; nt < 4; nt++) {
            int nn = nhalf * 32 + nt * 8 + gid;
            unsigned bb0 = *(const unsigned*)&sW[nn * AP + kt + 2 * tig];
            unsigned bb1 = *(const unsigned*)&sW[nn * AP + kt + 8 + 2 * tig];
            asm volatile(
                "mma.sync.aligned.m16n8k16.row.col.f32.f16.f16.f32 "
                "{%0,%1,%2,%3}, {%4,%5,%6,%7}, {%8,%9}, {%0,%1,%2,%3};"
                : "+f"(acc[nt][0]), "+f"(acc[nt][1]), "+f"(acc[nt][2]), "+f"(acc[nt][3])
                : "r"(a0), "r"(a1), "r"(a2), "r"(a3), "r"(bb0), "r"(bb1));
        }
    }

    int node0 = m0 + rowA;
    int node1 = node0 + 8;
    float ws0 = (node0 < n) ? wsv[node0] : 0.0f;
    float ws1 = (node1 < n) ? wsv[node1] : 0.0f;
#pragma unroll
    for (int nt = 0; nt < 4; nt++) {
        int c = nhalf * 32 + nt * 8 + 2 * tig;
        float ba0 = b2a[c], ba1 = b2a[c + 1];
        float bc0 = b2c[c], bc1 = b2c[c + 1];
        if (node0 < n)
            *(__half2*)&h2[(size_t)node0 * 64 + c] =
                __floats2half2_rn(elu1(acc[nt][0] + ws0 * ba0 + bc0),
                                  elu1(acc[nt][1] + ws0 * ba1 + bc1));
        if (node1 < n)
            *(__half2*)&h2[(size_t)node1 * 64 + c] =
                __floats2half2_rn(elu1(acc[nt][2] + ws1 * ba0 + bc0),
                                  elu1(acc[nt][3] + ws1 * ba1 + bc1));
    }
}

// ================= fused fc1+fc2+log_softmax =================
#define XFP 72
#define HSP 136
__global__ __launch_bounds__(256)
void fc12_kernel(const __half* __restrict__ Xh, const float* __restrict__ bf1,
                 const float* __restrict__ Wf2, const float* __restrict__ bf2,
                 float* __restrict__ out, int n) {
    extern __shared__ __half dsm[];
    __half* sX  = dsm;               // [64][XFP]
    __half* sW1 = dsm + 64 * XFP;    // [128][XFP]
    __half* sH  = dsm;               // [64][HSP] alias (used after phase A)
    __shared__ float sWf2[NCLS * HH];
    __shared__ float sbf2[NCLS];

    int tid = threadIdx.x;
    int wid = tid >> 5;
    int lane = tid & 31;
    int gid = lane >> 2;
    int tig = lane & 3;
    int mgrp = wid & 3;
    int nhalf = wid >> 2;
    int m0 = blockIdx.x * 64;

    for (int i = tid; i < 64 * 8; i += 256) {
        int m = i >> 3, kq = i & 7;
        int gm = m0 + m;
        int4 v = make_int4(0, 0, 0, 0);
        if (gm < n) v = *(const int4*)&Xh[(size_t)gm * 64 + kq * 8];
        *(int4*)&sX[m * XFP + kq * 8] = v;
    }
    for (int i = tid; i < 128 * 8; i += 256) {
        int nn = i >> 3, kq = i & 7;
        *(int4*)&sW1[nn * XFP + kq * 8] = *(const int4*)&g_wf1t[nn * 64 + kq * 8];
    }
    for (int i = tid; i < HH * NCLS; i += 256) {
        int k = i / NCLS, c = i % NCLS;
        sWf2[c * HH + k] = Wf2[i];
    }
    if (tid < NCLS) sbf2[tid] = bf2[tid];
    __syncthreads();

    float acc[8][4];
#pragma unroll
    for (int t = 0; t < 8; t++)
#pragma unroll
        for (int j = 0; j < 4; j++) acc[t][j] = 0.0f;

    int rowA = mgrp * 16 + gid;
#pragma unroll
    for (int kt = 0; kt < 64; kt += 16) {
        unsigned a0 = *(const unsigned*)&sX[rowA * XFP + kt + 2 * tig];
        unsigned a1 = *(const unsigned*)&sX[(rowA + 8) * XFP + kt + 2 * tig];
        unsigned a2 = *(const unsigned*)&sX[rowA * XFP + kt + 8 + 2 * tig];
        unsigned a3 = *(const unsigned*)&sX[(rowA + 8) * XFP + kt + 8 + 2 * tig];
#pragma unroll
        for (int nt = 0; nt < 8; nt++) {
            int nn = (nhalf * 8 + nt) * 8 + gid;
            unsigned bb0 = *(const unsigned*)&sW1[nn * XFP + kt + 2 * tig];
            unsigned bb1 = *(const unsigned*)&sW1[nn * XFP + kt + 8 + 2 * tig];
            asm volatile(
                "mma.sync.aligned.m16n8k16.row.col.f32.f16.f16.f32 "
                "{%0,%1,%2,%3}, {%4,%5,%6,%7}, {%8,%9}, {%0,%1,%2,%3};"
                : "+f"(acc[nt][0]), "+f"(acc[nt][1]), "+f"(acc[nt][2]), "+f"(acc[nt][3])
                : "r"(a0), "r"(a1), "r"(a2), "r"(a3), "r"(bb0), "r"(bb1));
        }
    }
    __syncthreads();   // done reading sX/sW1; sH may overwrite

#pragma unroll
    for (int nt = 0; nt < 8; nt++) {
        int c = (nhalf * 8 + nt) * 8 + 2 * tig;
        float b0 = bf1[c], b1 = bf1[c + 1];
        *(__half2*)&sH[rowA * HSP + c] =
            __floats2half2_rn(elu1(acc[nt][0] + b0), elu1(acc[nt][1] + b1));
        *(__half2*)&sH[(rowA + 8) * HSP + c] =
            __floats2half2_rn(elu1(acc[nt][2] + b0), elu1(acc[nt][3] + b1));
    }
    __syncthreads();

    for (int j = 0; j < 8; j++) {
        int r = wid * 8 + j;
        int node = m0 + r;
        if (node >= n) continue;
        int k0 = lane * 4;
        float2 f0 = __half22float2(*(const __half2*)&sH[r * HSP + k0]);
        float2 f1 = __half22float2(*(const __half2*)&sH[r * HSP + k0 + 2]);
        float a[NCLS];
#pragma unroll
        for (int c = 0; c < NCLS; c++) {
            const float* wr = &sWf2[c * HH + k0];
            a[c] = f0.x * wr[0] + f0.y * wr[1] + f1.x * wr[2] + f1.y * wr[3];
        }
#pragma unroll
        for (int off = 16; off > 0; off >>= 1) {
#pragma unroll
            for (int c = 0; c < NCLS; c++)
                a[c] += __shfl_xor_sync(0xFFFFFFFFu, a[c], off);
        }
        if (lane == 0) {
            float l[NCLS], mx = -1e30f;
#pragma unroll
            for (int c = 0; c < NCLS; c++) {
                l[c] = a[c] + sbf2[c];
                mx = fmaxf(mx, l[c]);
            }
            float se = 0.0f;
#pragma unroll
            for (int c = 0; c < NCLS; c++) se += expf(l[c] - mx);
            float lse = mx + logf(se);
#pragma unroll
            for (int c = 0; c < NCLS; c++) out[(size_t)node * NCLS + c] = l[c] - lse;
        }
    }
}
#define FC12_SMEM ((64 * XFP + 128 * XFP) * 2)   // 27648 bytes

// ---------------- launcher ----------------
static cudaStream_t g_s_csr = nullptr;
static cudaEvent_t  g_ev_fork = nullptr;
static cudaEvent_t  g_ev_join = nullptr;

extern "C" void kernel_launch(void* const* d_in, const int* in_sizes, int n_in,
                              void* d_out, int out_size) {
    const float* x   = (const float*)d_in[0];
    const int*   ei  = (const int*)d_in[1];
    const float* ea  = (const float*)d_in[2];
    const float* W1a = (const float*)d_in[3];
    const float* b1a = (const float*)d_in[4];
    const float* W1b = (const float*)d_in[5];
    const float* W1c = (const float*)d_in[6];
    const float* b1c = (const float*)d_in[7];
    const float* W2a = (const float*)d_in[8];
    const float* b2a = (const float*)d_in[9];
    const float* W2b = (const float*)d_in[10];
    const float* W2c = (const float*)d_in[11];
    const float* b2c = (const float*)d_in[12];
    const float* Wf1 = (const float*)d_in[13];
    const float* bf1 = (const float*)d_in[14];
    const float* Wf2 = (const float*)d_in[15];
    const float* bf2 = (const float*)d_in[16];
    float* out = (float*)d_out;

    const int* src = ei;
    const int* dst = ei + EE;

    __half *a1, *b1, *c1, *h1, *gG, *h2;
    float *wsv;
    cudaGetSymbolAddress((void**)&a1, g_a1);
    cudaGetSymbolAddress((void**)&b1, g_b1);
    cudaGetSymbolAddress((void**)&c1, g_c1);
    cudaGetSymbolAddress((void**)&h1, g_h1);
    cudaGetSymbolAddress((void**)&gG, g_g);
    cudaGetSymbolAddress((void**)&h2, g_h2);
    cudaGetSymbolAddress((void**)&wsv, g_wsum);

    if (g_s_csr == nullptr) {
        cudaStreamCreateWithFlags(&g_s_csr, cudaStreamNonBlocking);
        cudaEventCreateWithFlags(&g_ev_fork, cudaEventDisableTiming);
        cudaEventCreateWithFlags(&g_ev_join, cudaEventDisableTiming);
        cudaFuncSetAttribute(gemm1_tc_kernel,
                             cudaFuncAttributeMaxDynamicSharedMemorySize, GEMM1_SMEM);
        cudaFuncSetAttribute(fc12_kernel,
                             cudaFuncAttributeMaxDynamicSharedMemorySize, FC12_SMEM);
    }

    // Fork: scatter-only CSR build on side stream (g_cur pre-zeroed by previous run)
    cudaEventRecord(g_ev_fork, 0);
    cudaStreamWaitEvent(g_s_csr, g_ev_fork, 0);

    scatter_kernel<<<(EE / 4 + 255) / 256, 256, 0, g_s_csr>>>(
        (const int4*)src, (const int4*)dst, (const float4*)ea);
    cudaEventRecord(g_ev_join, g_s_csr);

    // conv1: W prep + tensor-core GEMM on main stream
    prep_w_kernel<<<(PREPW_TOTAL + 255) / 256, 256>>>(W1a, W1b, W1c, W2a, W2b, W2c, Wf1);
    gemm1_tc_kernel<<<(NN + 63) / 64, 256, GEMM1_SMEM>>>(x, b1a, b1c, a1, b1, c1, NN);

    cudaStreamWaitEvent(0, g_ev_join, 0);

    gather32_kernel<<<(NN + G32_NPB - 1) / G32_NPB, 256>>>(a1, b1, c1, h1, wsv, NN);
    gatherg_kernel<<<(NN + G32_NPB - 1) / G32_NPB, 256>>>(h1, gG, NN);
    gemm2f_kernel<<<(NN + 63) / 64, 256>>>(h1, gG, wsv, b2a, b2c, h2, NN);
    fc12_kernel<<<(NN + 63) / 64, 256, FC12_SMEM>>>(h2, bf1, Wf2, bf2, out, NN);
}